// round 15
// baseline (speedup 1.0000x reference)
#include <cuda_runtime.h>
#include <cuda_fp16.h>
#include <cstdint>

#define TT 2048
#define DD 64
#define NG 48
#define GSZ (TT*DD)        // 131072 elements per flat "head"

// ---- scratch (device globals; no allocation allowed) ----------------------
__device__ __half g_xh[8192*64];                        // x fp16 (hi only)
__device__ __half g_Wth[3*768*64], g_Wtl[3*768*64];     // W^T [mat][n][k] hi/lo
__device__ __half g_Woth[64*768], g_Wotl[64*768];       // Wo^T [n][k] hi/lo
__device__ __half g_Qh[(size_t)NG*GSZ];
__device__ __half g_Kh[(size_t)NG*GSZ];
__device__ __half g_Vh[(size_t)NG*GSZ];
__device__ __half g_Zh[(size_t)NG*GSZ];

// ---- helpers ---------------------------------------------------------------
__device__ __forceinline__ uint32_t smem_u32(const void* p) {
  uint32_t a;
  asm("{ .reg .u64 t; cvta.to.shared.u64 t, %1; cvt.u32.u64 %0, t; }"
      : "=r"(a) : "l"(p));
  return a;
}
__device__ __forceinline__ void ldmat4(uint32_t (&r)[4], uint32_t addr) {
  asm volatile("ldmatrix.sync.aligned.m8n8.x4.shared.b16 {%0,%1,%2,%3}, [%4];"
    : "=r"(r[0]), "=r"(r[1]), "=r"(r[2]), "=r"(r[3]) : "r"(addr));
}
__device__ __forceinline__ void ldmat4t(uint32_t (&r)[4], uint32_t addr) {
  asm volatile("ldmatrix.sync.aligned.m8n8.x4.trans.shared.b16 {%0,%1,%2,%3}, [%4];"
    : "=r"(r[0]), "=r"(r[1]), "=r"(r[2]), "=r"(r[3]) : "r"(addr));
}
__device__ __forceinline__ void mma16816(float (&c)[4], const uint32_t (&a)[4],
                                         uint32_t b0, uint32_t b1) {
  asm volatile("mma.sync.aligned.m16n8k16.row.col.f32.f16.f16.f32 "
    "{%0,%1,%2,%3}, {%4,%5,%6,%7}, {%8,%9}, {%0,%1,%2,%3};"
    : "+f"(c[0]), "+f"(c[1]), "+f"(c[2]), "+f"(c[3])
    : "r"(a[0]), "r"(a[1]), "r"(a[2]), "r"(a[3]), "r"(b0), "r"(b1));
}
__device__ __forceinline__ uint32_t pack_h2(float a, float b) {
  __half2 h = __floats2half2_rn(a, b);
  return *(uint32_t*)&h;
}
__device__ __forceinline__ void cpa16(uint32_t s, const void* g) {
  asm volatile("cp.async.cg.shared.global [%0], [%1], 16;" :: "r"(s), "l"(g));
}

// ---------------------------------------------------------------------------
// prep_all (R11): blocks [0,256) x -> g_xh fp16; [256,292) Wqkv; [292,304) Wo.
// ---------------------------------------------------------------------------
__global__ __launch_bounds__(256) void prep_all(
    const float* __restrict__ x,  const float* __restrict__ Wq,
    const float* __restrict__ Wk, const float* __restrict__ Wv,
    const float* __restrict__ Wo) {
  __shared__ float s[64*65];
  const int bid = blockIdx.x;
  const int tid = threadIdx.x;

  if (bid < 256) {
    const int t = bid*256 + tid;
    const float4 v0 = *(const float4*)(x + t*8);
    const float4 v1 = *(const float4*)(x + t*8 + 4);
    uint32_t h[4];
    h[0] = pack_h2(v0.x, v0.y); h[1] = pack_h2(v0.z, v0.w);
    h[2] = pack_h2(v1.x, v1.y); h[3] = pack_h2(v1.z, v1.w);
    *(uint4*)(g_xh + t*8) = make_uint4(h[0], h[1], h[2], h[3]);
    return;
  }

  if (bid < 292) {
    const int idx = bid - 256;
    const int nt = idx % 12, mat = idx / 12;
    const float* W = (mat == 0) ? Wq : ((mat == 1) ? Wk : Wv);
    const int n0 = nt*64;
    #pragma unroll
    for (int u = 0; u < 4; u++) {
      const int id2 = tid + 256*u;
      const int k = id2 >> 4, c4 = id2 & 15;
      const float4 v = *(const float4*)(W + k*768 + n0 + c4*4);
      s[(c4*4+0)*65 + k] = v.x; s[(c4*4+1)*65 + k] = v.y;
      s[(c4*4+2)*65 + k] = v.z; s[(c4*4+3)*65 + k] = v.w;
    }
    __syncthreads();
    const int n = tid >> 2, k0 = (tid & 3) * 16;
    uint32_t h[8], l[8];
    #pragma unroll
    for (int i = 0; i < 8; i++) {
      const float a = s[n*65 + k0 + 2*i], b = s[n*65 + k0 + 2*i + 1];
      const float ha = __half2float(__float2half_rn(a));
      const float hb = __half2float(__float2half_rn(b));
      h[i] = pack_h2(a, b);
      l[i] = pack_h2(a - ha, b - hb);
    }
    __half* dh = g_Wth + (size_t)(mat*768 + n0 + n)*64 + k0;
    __half* dl = g_Wtl + (size_t)(mat*768 + n0 + n)*64 + k0;
    ((uint4*)dh)[0] = make_uint4(h[0], h[1], h[2], h[3]);
    ((uint4*)dh)[1] = make_uint4(h[4], h[5], h[6], h[7]);
    ((uint4*)dl)[0] = make_uint4(l[0], l[1], l[2], l[3]);
    ((uint4*)dl)[1] = make_uint4(l[4], l[5], l[6], l[7]);
    return;
  }

  {
    const int kt = bid - 292;
    const int k0g = kt*64;
    #pragma unroll
    for (int u = 0; u < 4; u++) {
      const int id2 = tid + 256*u;
      const int k = id2 >> 4, c4 = id2 & 15;
      const float4 v = *(const float4*)(Wo + (size_t)(k0g + k)*64 + c4*4);
      s[(c4*4+0)*65 + k] = v.x; s[(c4*4+1)*65 + k] = v.y;
      s[(c4*4+2)*65 + k] = v.z; s[(c4*4+3)*65 + k] = v.w;
    }
    __syncthreads();
    const int n = tid >> 2, k0 = (tid & 3) * 16;
    uint32_t h[8], l[8];
    #pragma unroll
    for (int i = 0; i < 8; i++) {
      const float a = s[n*65 + k0 + 2*i], b = s[n*65 + k0 + 2*i + 1];
      const float ha = __half2float(__float2half_rn(a));
      const float hb = __half2float(__float2half_rn(b));
      h[i] = pack_h2(a, b);
      l[i] = pack_h2(a - ha, b - hb);
    }
    __half* dh = g_Woth + (size_t)n*768 + k0g + k0;
    __half* dl = g_Wotl + (size_t)n*768 + k0g + k0;
    ((uint4*)dh)[0] = make_uint4(h[0], h[1], h[2], h[3]);
    ((uint4*)dh)[1] = make_uint4(h[4], h[5], h[6], h[7]);
    ((uint4*)dl)[0] = make_uint4(l[0], l[1], l[2], l[3]);
    ((uint4*)dl)[1] = make_uint4(l[4], l[5], l[6], l[7]);
  }
}

// ---------------------------------------------------------------------------
// qkv_mma (R11): QKV = xh @ (Wh + Wl).  grid (12, 64, 3), block 256.
// ---------------------------------------------------------------------------
#define QK_XH 0
#define QK_WH 16384
#define QK_WL 24576
#define QK_SMEM 32768

__global__ __launch_bounds__(256) void qkv_mma() {
  extern __shared__ char smc[];
  const uint32_t sb = smem_u32(smc);
  const uint32_t sXh = sb + QK_XH;
  const uint32_t sWh = sb + QK_WH, sWl = sb + QK_WL;
  const int nt = blockIdx.x, mt = blockIdx.y, mat = blockIdx.z;
  const int tid = threadIdx.x;
  const int wid = tid >> 5, l = tid & 31;
  const int wr = wid & 3, wc = wid >> 2;
  const int m0 = mt*128, n0 = nt*64;

  const int arow = (l & 7) + (((l >> 3) & 1) << 3);
  const int achk = l >> 4;
  const int brow = (l & 7) + ((l >> 4) << 3);
  const int bchk = (l >> 3) & 1;
  const int axor = l & 7, bxor = l & 7;

  #pragma unroll
  for (int u = 0; u < 4; u++) {
    const int idx = tid + 256*u;
    const int row = idx >> 3, c = idx & 7;
    const uint32_t go = (uint32_t)(m0 + row)*128 + c*16;
    const uint32_t so = (uint32_t)row*128 + (uint32_t)((c ^ (row & 7)) << 4);
    *(uint4*)(smc + QK_XH + so) = *(const uint4*)((const char*)g_xh + go);
  }
  #pragma unroll
  for (int u = 0; u < 2; u++) {
    const int idx = tid + 256*u;
    const int row = idx >> 3, c = idx & 7;
    const uint32_t go = (uint32_t)(mat*768 + n0 + row)*128 + c*16;
    const uint32_t so = (uint32_t)row*128 + (uint32_t)((c ^ (row & 7)) << 4);
    *(uint4*)(smc + QK_WH + so) = *(const uint4*)((const char*)g_Wth + go);
    *(uint4*)(smc + QK_WL + so) = *(const uint4*)((const char*)g_Wtl + go);
  }
  __syncthreads();

  float acc[2][4][4] = {};
  #pragma unroll
  for (int ks = 0; ks < 4; ks++) {
    const int kc = 2*ks;
    uint32_t aH0[4], aH1[4], bH0[4], bH1[4], bL0[4], bL1[4];
    const uint32_t ac = (uint32_t)(((kc + achk) ^ axor) << 4);
    const uint32_t bc = (uint32_t)(((kc + bchk) ^ bxor) << 4);
    ldmat4(aH0, sXh + (uint32_t)(wr*32      + arow)*128 + ac);
    ldmat4(aH1, sXh + (uint32_t)(wr*32 + 16 + arow)*128 + ac);
    ldmat4(bH0, sWh + (uint32_t)(wc*32      + brow)*128 + bc);
    ldmat4(bH1, sWh + (uint32_t)(wc*32 + 16 + brow)*128 + bc);
    ldmat4(bL0, sWl + (uint32_t)(wc*32      + brow)*128 + bc);
    ldmat4(bL1, sWl + (uint32_t)(wc*32 + 16 + brow)*128 + bc);
    mma16816(acc[0][0], aH0, bH0[0], bH0[1]); mma16816(acc[0][1], aH0, bH0[2], bH0[3]);
    mma16816(acc[0][2], aH0, bH1[0], bH1[1]); mma16816(acc[0][3], aH0, bH1[2], bH1[3]);
    mma16816(acc[1][0], aH1, bH0[0], bH0[1]); mma16816(acc[1][1], aH1, bH0[2], bH0[3]);
    mma16816(acc[1][2], aH1, bH1[0], bH1[1]); mma16816(acc[1][3], aH1, bH1[2], bH1[3]);
    mma16816(acc[0][0], aH0, bL0[0], bL0[1]); mma16816(acc[0][1], aH0, bL0[2], bL0[3]);
    mma16816(acc[0][2], aH0, bL1[0], bL1[1]); mma16816(acc[0][3], aH0, bL1[2], bL1[3]);
    mma16816(acc[1][0], aH1, bL0[0], bL0[1]); mma16816(acc[1][1], aH1, bL0[2], bL0[3]);
    mma16816(acc[1][2], aH1, bL1[0], bL1[1]); mma16816(acc[1][3], aH1, bL1[2], bL1[3]);
  }

  #pragma unroll
  for (int mi = 0; mi < 2; mi++) {
    const int r0 = wr*32 + mi*16 + (l >> 2);
    #pragma unroll
    for (int ni = 0; ni < 4; ni++) {
      const int d = wc*32 + ni*8 + 2*(l & 3);
      #pragma unroll
      for (int hh = 0; hh < 2; hh++) {
        const int r = r0 + 8*hh;
        const float a = acc[mi][ni][2*hh+0], bb = acc[mi][ni][2*hh+1];
        const size_t off = (size_t)(m0 + r)*768 + n0 + d;
        if (mat == 0) {
          *(uint32_t*)(g_Qh + off) = pack_h2(a, bb);
        } else if (mat == 1) {
          *(uint32_t*)(g_Kh + off) = pack_h2(a, bb);
        } else {
          *(uint32_t*)(g_Vh + off) = pack_h2(a, bb);
        }
      }
    }
  }
}

// ---------------------------------------------------------------------------
// HMMA flash attention (R11-proven): register-resident P, 4 CTAs/SM.
// grid (32 i-tiles, 48 heads), 128 threads = 4 warps.
// ---------------------------------------------------------------------------
#define OFF_KH 0         // 8KB (64 rows)
#define OFF_Q  8192      // double buffer, stride 8192
#define OFF_V  24576     // double buffer, stride 8192
#define SMEM_ATT 40960

__global__ __launch_bounds__(128, 4) void attn_mma() {
  extern __shared__ char smc[];
  const uint32_t sb = smem_u32(smc);
  const uint32_t sKh = sb + OFF_KH;

  const int g = blockIdx.y, it = blockIdx.x;
  const int tid = threadIdx.x;
  const int w = tid >> 5, l = tid & 31;

  const char* Qg  = (const char*)(g_Qh + (size_t)g*GSZ);
  const char* Khg = (const char*)(g_Kh + (size_t)g*GSZ);
  const char* Vg  = (const char*)(g_Vh + (size_t)g*GSZ);

  const int arow = (l & 7) + (((l >> 3) & 1) << 3);
  const int achk = l >> 4;
  const int brow = (l & 7) + ((l >> 4) << 3);
  const int bchk = (l >> 3) & 1;
  const int axor = l & 7, bxor = l & 7;

  // K i-tile (plain loads, once)
  #pragma unroll
  for (int u = 0; u < 4; u++) {
    const int idx = tid + 128*u;
    const int row = idx >> 3, c = idx & 7;
    const uint32_t go = (uint32_t)(it*64 + row)*128 + c*16;
    const uint32_t so = (uint32_t)row*128 + (uint32_t)((c ^ (row & 7)) << 4);
    *(uint4*)(smc + OFF_KH + so) = *(const uint4*)(Khg + go);
  }

  // prologue: prefetch jt=0 into buffer 0
  #pragma unroll
  for (int u = 0; u < 4; u++) {
    const int idx = tid + 128*u;
    const int row = idx >> 3, c = idx & 7;
    const uint32_t go = (uint32_t)row*128 + c*16;
    const uint32_t so = (uint32_t)row*128 + (uint32_t)((c ^ (row & 7)) << 4);
    cpa16(sb + OFF_Q + so, Qg + go);
    cpa16(sb + OFF_V + so, Vg + go);
  }
  asm volatile("cp.async.commit_group;" ::: "memory");

  float zacc[8][4] = {};
  float lrow[2] = {0.f, 0.f};

  for (int jt = 0; jt < 32; jt++) {
    const uint32_t qb = sb + OFF_Q + (uint32_t)(jt & 1)*8192;
    const uint32_t vb = sb + OFF_V + (uint32_t)(jt & 1)*8192;

    asm volatile("cp.async.wait_group 0;" ::: "memory");
    __syncthreads();

    if (jt < 31) {
      const uint32_t qn = sb + OFF_Q + (uint32_t)((jt + 1) & 1)*8192;
      const uint32_t vn = sb + OFF_V + (uint32_t)((jt + 1) & 1)*8192;
      #pragma unroll
      for (int u = 0; u < 4; u++) {
        const int idx = tid + 128*u;
        const int row = idx >> 3, c = idx & 7;
        const uint32_t go = (uint32_t)((jt + 1)*64 + row)*128 + c*16;
        const uint32_t so = (uint32_t)row*128 + (uint32_t)((c ^ (row & 7)) << 4);
        cpa16(qn + so, Qg + go);
        cpa16(vn + so, Vg + go);
      }
      asm volatile("cp.async.commit_group;" ::: "memory");
    }

    // ---- S = K . Q^T ----
    float sacc[8][4] = {};
    #pragma unroll
    for (int ks = 0; ks < 4; ks++) {
      const int kc = 2*ks;
      uint32_t a[4];
      const uint32_t ac = (uint32_t)(((kc + achk) ^ axor) << 4);
      const uint32_t bc = (uint32_t)(((kc + bchk) ^ bxor) << 4);
      ldmat4(a, sKh + (uint32_t)(w*16 + arow)*128 + ac);
      #pragma unroll
      for (int jb = 0; jb < 4; jb++) {
        uint32_t q[4];
        ldmat4(q, qb + (uint32_t)(jb*16 + brow)*128 + bc);
        mma16816(sacc[2*jb],   a, q[0], q[1]);
        mma16816(sacc[2*jb+1], a, q[2], q[3]);
      }
    }

    // ---- softmax (no max) in registers; P packed as A-fragments ----
    uint32_t pa[8], pb[8];
    #pragma unroll
    for (int nt = 0; nt < 8; nt++) {
      const float p0 = __expf(sacc[nt][0] * 0.125f);
      const float p1 = __expf(sacc[nt][1] * 0.125f);
      const float p2 = __expf(sacc[nt][2] * 0.125f);
      const float p3 = __expf(sacc[nt][3] * 0.125f);
      lrow[0] += p0 + p1;
      lrow[1] += p2 + p3;
      pa[nt] = pack_h2(p0, p1);
      pb[nt] = pack_h2(p2, p3);
    }

    // ---- Z += P . V ----
    #pragma unroll
    for (int kj = 0; kj < 4; kj++) {
      const uint32_t A[4] = {pa[2*kj], pb[2*kj], pa[2*kj+1], pb[2*kj+1]};
      #pragma unroll
      for (int d4 = 0; d4 < 4; d4++) {
        uint32_t v[4];
        ldmat4t(v, vb + (uint32_t)(16*kj + arow)*128 +
                   (uint32_t)(((2*d4 + achk) ^ axor) << 4));
        mma16816(zacc[2*d4],   A, v[0], v[1]);
        mma16816(zacc[2*d4+1], A, v[2], v[3]);
      }
    }
  }

  // ---- final row sums and epilogue (Zh only) ----
  #pragma unroll
  for (int h = 0; h < 2; h++) {
    float v = lrow[h];
    v += __shfl_xor_sync(0xffffffffu, v, 1);
    v += __shfl_xor_sync(0xffffffffu, v, 2);
    lrow[h] = v;
  }
  const float inv0 = 1.f / lrow[0];
  const float inv1 = 1.f / lrow[1];

  __half* Zh = g_Zh + (size_t)g*GSZ + (size_t)it*64*64;
  const int r0 = w*16 + (l >> 2);
  #pragma unroll
  for (int nt = 0; nt < 8; nt++) {
    const int c = nt*8 + 2*(l & 3);
    *(uint32_t*)(Zh + (size_t)r0*64 + c) =
        pack_h2(zacc[nt][0]*inv0, zacc[nt][1]*inv0);
    *(uint32_t*)(Zh + (size_t)(r0+8)*64 + c) =
        pack_h2(zacc[nt][2]*inv1, zacc[nt][3]*inv1);
  }
}

// ---------------------------------------------------------------------------
// out_mma: out = Zh @ (Wh + Wl), 3-stage cp.async ring (wait_group 1) to
// hide load latency (1 CTA/SM -> smem is free).  grid 128, block 256.
// Stage s at s*24576: Z +0, Wh +8192, Wl +16384.
// ---------------------------------------------------------------------------
#define OG_STAGE 24576
#define OG_SMEM  (3*24576)

__global__ __launch_bounds__(256) void out_mma(float* __restrict__ out) {
  extern __shared__ char smc[];
  const uint32_t sb = smem_u32(smc);
  const int mt = blockIdx.x;
  const int tid = threadIdx.x;
  const int wid = tid >> 5, l = tid & 31;
  const int wr = wid & 3, wc = wid >> 2;
  const int m0 = mt*64;

  const int arow = (l & 7) + (((l >> 3) & 1) << 3);
  const int achk = l >> 4;
  const int brow = (l & 7) + ((l >> 4) << 3);
  const int bchk = (l >> 3) & 1;
  const int axor = l & 7, bxor = l & 7;

  // prologue: prefetch kt=0 and kt=1 into stages 0,1
  #pragma unroll
  for (int p = 0; p < 2; p++) {
    const uint32_t st = sb + (uint32_t)p*OG_STAGE;
    #pragma unroll
    for (int u = 0; u < 2; u++) {
      const int idx = tid + 256*u;
      const int row = idx >> 3, c = idx & 7;
      const uint32_t zgo = (uint32_t)(m0 + row)*1536 + (uint32_t)p*128 + c*16;
      const uint32_t wgo = (uint32_t)row*1536 + (uint32_t)p*128 + c*16;
      const uint32_t so = (uint32_t)row*128 + (uint32_t)((c ^ (row & 7)) << 4);
      cpa16(st + so,         (const char*)g_Zh + zgo);
      cpa16(st + 8192 + so,  (const char*)g_Woth + wgo);
      cpa16(st + 16384 + so, (const char*)g_Wotl + wgo);
    }
    asm volatile("cp.async.commit_group;" ::: "memory");
  }

  float acc[4][4] = {};
  int stage = 0, nstage = 2;

  for (int kt = 0; kt < 12; kt++) {
    const uint32_t st = sb + (uint32_t)stage*OG_STAGE;
    const uint32_t sZh = st, sWh = st + 8192, sWl = st + 16384;

    asm volatile("cp.async.wait_group 1;" ::: "memory");   // group(kt) done
    __syncthreads();

    if (kt < 10) {
      const uint32_t ns = sb + (uint32_t)nstage*OG_STAGE;
      #pragma unroll
      for (int u = 0; u < 2; u++) {
        const int idx = tid + 256*u;
        const int row = idx >> 3, c = idx & 7;
        const uint32_t zgo = (uint32_t)(m0 + row)*1536 + (uint32_t)(kt+2)*128 + c*16;
        const uint32_t wgo = (uint32_t)row*1536 + (uint32_t)(kt+2)*128 + c*16;
        const uint32_t so = (uint32_t)row*128 + (uint32_t)((c ^ (row & 7)) << 4);
        cpa16(ns + so,         (const char*)g_Zh + zgo);
        cpa16(ns + 8192 + so,  (const char*)g_Woth + wgo);
        cpa16(ns + 16384 + so, (const char*)g_Wotl + wgo);
      }
      asm volatile("cp.async.commit_group;" ::: "memory");
    } else {
      // keep wait_group accounting uniform: commit an empty group
      asm volatile("cp.async.commit_group;" ::: "memory");
    }

    #pragma unroll
    for (int ks = 0; ks < 4; ks++) {
      const int kc = 2*ks;
      uint32_t aH[4], bH0[4], bH1[4], bL0[4], bL1[4];
      const uint32_t ac = (uint32_t)(((kc + achk) ^ axor) << 4);
      const uint32_t bc = (uint32_t)(((kc + bchk) ^ bxor) << 4);
      ldmat4(aH, sZh + (uint32_t)(wr*16 + arow)*128 + ac);
      ldmat4(bH0, sWh + (uint32_t)(wc*32      + brow)*128 + bc);
      ldmat4(bH1, sWh + (uint32_t)(wc*32 + 16 + brow)*128 + bc);
      ldmat4(bL0, sWl + (uint32_t)(wc*32      + brow)*128 + bc);
      ldmat4(bL1, sWl + (uint32_t)(wc*32 + 16 + brow)*128 + bc);
      mma16816(acc[0], aH, bH0[0], bH0[1]); mma16816(acc[1], aH, bH0[2], bH0[3]);
      mma16816(acc[2], aH, bH1[0], bH1[1]); mma16816(acc[3], aH, bH1[2], bH1[3]);
      mma16816(acc[0], aH, bL0[0], bL0[1]); mma16816(acc[1], aH, bL0[2], bL0[3]);
      mma16816(acc[2], aH, bL1[0], bL1[1]); mma16816(acc[3], aH, bL1[2], bL1[3]);
    }

    stage = (stage + 1 == 3) ? 0 : stage + 1;
    nstage = (nstage + 1 == 3) ? 0 : nstage + 1;
  }

  const int r0 = m0 + wr*16 + (l >> 2);
  #pragma unroll
  for (int ni = 0; ni < 4; ni++) {
    const int n = wc*32 + ni*8 + 2*(l & 3);
    *(float2*)(out + (size_t)r0*64 + n)       = make_float2(acc[ni][0], acc[ni][1]);
    *(float2*)(out + (size_t)(r0 + 8)*64 + n) = make_float2(acc[ni][2], acc[ni][3]);
  }
}

// ---------------------------------------------------------------------------
extern "C" void kernel_launch(void* const* d_in, const int* in_sizes, int n_in,
                              void* d_out, int out_size) {
  const float* x  = (const float*)d_in[0];
  const float* Wq = (const float*)d_in[1];
  const float* Wk = (const float*)d_in[2];
  const float* Wv = (const float*)d_in[3];
  const float* Wo = (const float*)d_in[4];
  float* out = (float*)d_out;

  prep_all<<<304, 256>>>(x, Wq, Wk, Wv, Wo);

  cudaFuncSetAttribute(qkv_mma, cudaFuncAttributeMaxDynamicSharedMemorySize,
                       QK_SMEM);
  qkv_mma<<<dim3(12, 64, 3), 256, QK_SMEM>>>();

  cudaFuncSetAttribute(attn_mma, cudaFuncAttributeMaxDynamicSharedMemorySize,
                       SMEM_ATT);
  attn_mma<<<dim3(32, 48), 128, SMEM_ATT>>>();

  cudaFuncSetAttribute(out_mma, cudaFuncAttributeMaxDynamicSharedMemorySize,
                       OG_SMEM);
  out_mma<<<128, 256, OG_SMEM>>>(out);
}

// round 16
// speedup vs baseline: 1.5351x; 1.5351x over previous
#include <cuda_runtime.h>
#include <cuda_fp16.h>
#include <cstdint>

#define TT 2048
#define DD 64
#define NG 48
#define GSZ (TT*DD)        // 131072 elements per flat "head"

// ---- scratch (device globals; no allocation allowed) ----------------------
__device__ __half g_xh[8192*64];                        // x fp16 (hi only)
__device__ __half g_Wth[3*768*64], g_Wtl[3*768*64];     // W^T [mat][n][k] hi/lo
__device__ __half g_Woth[64*768], g_Wotl[64*768];       // Wo^T [n][k] hi/lo
__device__ __half g_Qh[(size_t)NG*GSZ];
__device__ __half g_Kh[(size_t)NG*GSZ];
__device__ __half g_Vh[(size_t)NG*GSZ];
__device__ __half g_Zh[(size_t)NG*GSZ];

// ---- helpers ---------------------------------------------------------------
__device__ __forceinline__ uint32_t smem_u32(const void* p) {
  uint32_t a;
  asm("{ .reg .u64 t; cvta.to.shared.u64 t, %1; cvt.u32.u64 %0, t; }"
      : "=r"(a) : "l"(p));
  return a;
}
__device__ __forceinline__ void ldmat4(uint32_t (&r)[4], uint32_t addr) {
  asm volatile("ldmatrix.sync.aligned.m8n8.x4.shared.b16 {%0,%1,%2,%3}, [%4];"
    : "=r"(r[0]), "=r"(r[1]), "=r"(r[2]), "=r"(r[3]) : "r"(addr));
}
__device__ __forceinline__ void ldmat4t(uint32_t (&r)[4], uint32_t addr) {
  asm volatile("ldmatrix.sync.aligned.m8n8.x4.trans.shared.b16 {%0,%1,%2,%3}, [%4];"
    : "=r"(r[0]), "=r"(r[1]), "=r"(r[2]), "=r"(r[3]) : "r"(addr));
}
__device__ __forceinline__ void mma16816(float (&c)[4], const uint32_t (&a)[4],
                                         uint32_t b0, uint32_t b1) {
  asm volatile("mma.sync.aligned.m16n8k16.row.col.f32.f16.f16.f32 "
    "{%0,%1,%2,%3}, {%4,%5,%6,%7}, {%8,%9}, {%0,%1,%2,%3};"
    : "+f"(c[0]), "+f"(c[1]), "+f"(c[2]), "+f"(c[3])
    : "r"(a[0]), "r"(a[1]), "r"(a[2]), "r"(a[3]), "r"(b0), "r"(b1));
}
__device__ __forceinline__ uint32_t pack_h2(float a, float b) {
  __half2 h = __floats2half2_rn(a, b);
  return *(uint32_t*)&h;
}
__device__ __forceinline__ void cpa16(uint32_t s, const void* g) {
  asm volatile("cp.async.cg.shared.global [%0], [%1], 16;" :: "r"(s), "l"(g));
}

// ---------------------------------------------------------------------------
// prep_all: one launch for all preprocessing.
//   blocks [0,256):   x fp32 -> g_xh fp16 (hi only)
//   blocks [256,292): W{q,k,v} -> Wt [mat][n][k] fp16 hi/lo  (idx = nt + 12*mat)
//   blocks [292,304): Wo -> Wot [64][768] fp16 hi/lo          (kt = idx)
// block 256 threads.
// ---------------------------------------------------------------------------
__global__ __launch_bounds__(256) void prep_all(
    const float* __restrict__ x,  const float* __restrict__ Wq,
    const float* __restrict__ Wk, const float* __restrict__ Wv,
    const float* __restrict__ Wo) {
  __shared__ float s[64*65];
  const int bid = blockIdx.x;
  const int tid = threadIdx.x;

  if (bid < 256) {
    const int t = bid*256 + tid;
    const float4 v0 = *(const float4*)(x + t*8);
    const float4 v1 = *(const float4*)(x + t*8 + 4);
    uint32_t h[4];
    h[0] = pack_h2(v0.x, v0.y); h[1] = pack_h2(v0.z, v0.w);
    h[2] = pack_h2(v1.x, v1.y); h[3] = pack_h2(v1.z, v1.w);
    *(uint4*)(g_xh + t*8) = make_uint4(h[0], h[1], h[2], h[3]);
    return;
  }

  if (bid < 292) {
    const int idx = bid - 256;
    const int nt = idx % 12, mat = idx / 12;
    const float* W = (mat == 0) ? Wq : ((mat == 1) ? Wk : Wv);
    const int n0 = nt*64;
    #pragma unroll
    for (int u = 0; u < 4; u++) {
      const int id2 = tid + 256*u;
      const int k = id2 >> 4, c4 = id2 & 15;
      const float4 v = *(const float4*)(W + k*768 + n0 + c4*4);
      s[(c4*4+0)*65 + k] = v.x; s[(c4*4+1)*65 + k] = v.y;
      s[(c4*4+2)*65 + k] = v.z; s[(c4*4+3)*65 + k] = v.w;
    }
    __syncthreads();
    const int n = tid >> 2, k0 = (tid & 3) * 16;
    uint32_t h[8], l[8];
    #pragma unroll
    for (int i = 0; i < 8; i++) {
      const float a = s[n*65 + k0 + 2*i], b = s[n*65 + k0 + 2*i + 1];
      const float ha = __half2float(__float2half_rn(a));
      const float hb = __half2float(__float2half_rn(b));
      h[i] = pack_h2(a, b);
      l[i] = pack_h2(a - ha, b - hb);
    }
    __half* dh = g_Wth + (size_t)(mat*768 + n0 + n)*64 + k0;
    __half* dl = g_Wtl + (size_t)(mat*768 + n0 + n)*64 + k0;
    ((uint4*)dh)[0] = make_uint4(h[0], h[1], h[2], h[3]);
    ((uint4*)dh)[1] = make_uint4(h[4], h[5], h[6], h[7]);
    ((uint4*)dl)[0] = make_uint4(l[0], l[1], l[2], l[3]);
    ((uint4*)dl)[1] = make_uint4(l[4], l[5], l[6], l[7]);
    return;
  }

  {
    const int kt = bid - 292;
    const int k0g = kt*64;
    #pragma unroll
    for (int u = 0; u < 4; u++) {
      const int id2 = tid + 256*u;
      const int k = id2 >> 4, c4 = id2 & 15;
      const float4 v = *(const float4*)(Wo + (size_t)(k0g + k)*64 + c4*4);
      s[(c4*4+0)*65 + k] = v.x; s[(c4*4+1)*65 + k] = v.y;
      s[(c4*4+2)*65 + k] = v.z; s[(c4*4+3)*65 + k] = v.w;
    }
    __syncthreads();
    const int n = tid >> 2, k0 = (tid & 3) * 16;
    uint32_t h[8], l[8];
    #pragma unroll
    for (int i = 0; i < 8; i++) {
      const float a = s[n*65 + k0 + 2*i], b = s[n*65 + k0 + 2*i + 1];
      const float ha = __half2float(__float2half_rn(a));
      const float hb = __half2float(__float2half_rn(b));
      h[i] = pack_h2(a, b);
      l[i] = pack_h2(a - ha, b - hb);
    }
    __half* dh = g_Woth + (size_t)n*768 + k0g + k0;
    __half* dl = g_Wotl + (size_t)n*768 + k0g + k0;
    ((uint4*)dh)[0] = make_uint4(h[0], h[1], h[2], h[3]);
    ((uint4*)dh)[1] = make_uint4(h[4], h[5], h[6], h[7]);
    ((uint4*)dl)[0] = make_uint4(l[0], l[1], l[2], l[3]);
    ((uint4*)dl)[1] = make_uint4(l[4], l[5], l[6], l[7]);
  }
}

// ---------------------------------------------------------------------------
// qkv_mma: QKV = xh @ (Wh + Wl) via HMMA (2-term split; x lo dropped).
// grid (12 nt, 64 mt, 3 mat), block 256, tile 128m x 64n.
// ---------------------------------------------------------------------------
#define QK_XH 0
#define QK_WH 16384
#define QK_WL 24576
#define QK_SMEM 32768

__global__ __launch_bounds__(256) void qkv_mma() {
  extern __shared__ char smc[];
  const uint32_t sb = smem_u32(smc);
  const uint32_t sXh = sb + QK_XH;
  const uint32_t sWh = sb + QK_WH, sWl = sb + QK_WL;
  const int nt = blockIdx.x, mt = blockIdx.y, mat = blockIdx.z;
  const int tid = threadIdx.x;
  const int wid = tid >> 5, l = tid & 31;
  const int wr = wid & 3, wc = wid >> 2;
  const int m0 = mt*128, n0 = nt*64;

  const int arow = (l & 7) + (((l >> 3) & 1) << 3);
  const int achk = l >> 4;
  const int brow = (l & 7) + ((l >> 4) << 3);
  const int bchk = (l >> 3) & 1;
  const int axor = l & 7, bxor = l & 7;

  #pragma unroll
  for (int u = 0; u < 4; u++) {
    const int idx = tid + 256*u;
    const int row = idx >> 3, c = idx & 7;
    const uint32_t go = (uint32_t)(m0 + row)*128 + c*16;
    const uint32_t so = (uint32_t)row*128 + (uint32_t)((c ^ (row & 7)) << 4);
    *(uint4*)(smc + QK_XH + so) = *(const uint4*)((const char*)g_xh + go);
  }
  #pragma unroll
  for (int u = 0; u < 2; u++) {
    const int idx = tid + 256*u;
    const int row = idx >> 3, c = idx & 7;
    const uint32_t go = (uint32_t)(mat*768 + n0 + row)*128 + c*16;
    const uint32_t so = (uint32_t)row*128 + (uint32_t)((c ^ (row & 7)) << 4);
    *(uint4*)(smc + QK_WH + so) = *(const uint4*)((const char*)g_Wth + go);
    *(uint4*)(smc + QK_WL + so) = *(const uint4*)((const char*)g_Wtl + go);
  }
  __syncthreads();

  float acc[2][4][4] = {};
  #pragma unroll
  for (int ks = 0; ks < 4; ks++) {
    const int kc = 2*ks;
    uint32_t aH0[4], aH1[4], bH0[4], bH1[4], bL0[4], bL1[4];
    const uint32_t ac = (uint32_t)(((kc + achk) ^ axor) << 4);
    const uint32_t bc = (uint32_t)(((kc + bchk) ^ bxor) << 4);
    ldmat4(aH0, sXh + (uint32_t)(wr*32      + arow)*128 + ac);
    ldmat4(aH1, sXh + (uint32_t)(wr*32 + 16 + arow)*128 + ac);
    ldmat4(bH0, sWh + (uint32_t)(wc*32      + brow)*128 + bc);
    ldmat4(bH1, sWh + (uint32_t)(wc*32 + 16 + brow)*128 + bc);
    ldmat4(bL0, sWl + (uint32_t)(wc*32      + brow)*128 + bc);
    ldmat4(bL1, sWl + (uint32_t)(wc*32 + 16 + brow)*128 + bc);
    mma16816(acc[0][0], aH0, bH0[0], bH0[1]); mma16816(acc[0][1], aH0, bH0[2], bH0[3]);
    mma16816(acc[0][2], aH0, bH1[0], bH1[1]); mma16816(acc[0][3], aH0, bH1[2], bH1[3]);
    mma16816(acc[1][0], aH1, bH0[0], bH0[1]); mma16816(acc[1][1], aH1, bH0[2], bH0[3]);
    mma16816(acc[1][2], aH1, bH1[0], bH1[1]); mma16816(acc[1][3], aH1, bH1[2], bH1[3]);
    mma16816(acc[0][0], aH0, bL0[0], bL0[1]); mma16816(acc[0][1], aH0, bL0[2], bL0[3]);
    mma16816(acc[0][2], aH0, bL1[0], bL1[1]); mma16816(acc[0][3], aH0, bL1[2], bL1[3]);
    mma16816(acc[1][0], aH1, bL0[0], bL0[1]); mma16816(acc[1][1], aH1, bL0[2], bL0[3]);
    mma16816(acc[1][2], aH1, bL1[0], bL1[1]); mma16816(acc[1][3], aH1, bL1[2], bL1[3]);
  }

  #pragma unroll
  for (int mi = 0; mi < 2; mi++) {
    const int r0 = wr*32 + mi*16 + (l >> 2);
    #pragma unroll
    for (int ni = 0; ni < 4; ni++) {
      const int d = wc*32 + ni*8 + 2*(l & 3);
      #pragma unroll
      for (int hh = 0; hh < 2; hh++) {
        const int r = r0 + 8*hh;
        const float a = acc[mi][ni][2*hh+0], bb = acc[mi][ni][2*hh+1];
        const size_t off = (size_t)(m0 + r)*768 + n0 + d;
        if (mat == 0) {
          *(uint32_t*)(g_Qh + off) = pack_h2(a, bb);
        } else if (mat == 1) {
          *(uint32_t*)(g_Kh + off) = pack_h2(a, bb);
        } else {
          *(uint32_t*)(g_Vh + off) = pack_h2(a, bb);
        }
      }
    }
  }
}

// ---------------------------------------------------------------------------
// HMMA flash attention, register-resident P, 4-CTA-per-SM config.
// grid (32 i-tiles, 48 heads), 128 threads = 4 warps.  Z written fp16 (hi only).
// ---------------------------------------------------------------------------
#define OFF_KH 0         // 8KB (64 rows)
#define OFF_Q  8192      // double buffer, stride 8192
#define OFF_V  24576     // double buffer, stride 8192
#define SMEM_ATT 40960

__global__ __launch_bounds__(128, 4) void attn_mma() {
  extern __shared__ char smc[];
  const uint32_t sb = smem_u32(smc);
  const uint32_t sKh = sb + OFF_KH;

  const int g = blockIdx.y, it = blockIdx.x;
  const int tid = threadIdx.x;
  const int w = tid >> 5, l = tid & 31;

  const char* Qg  = (const char*)(g_Qh + (size_t)g*GSZ);
  const char* Khg = (const char*)(g_Kh + (size_t)g*GSZ);
  const char* Vg  = (const char*)(g_Vh + (size_t)g*GSZ);

  const int arow = (l & 7) + (((l >> 3) & 1) << 3);
  const int achk = l >> 4;
  const int brow = (l & 7) + ((l >> 4) << 3);
  const int bchk = (l >> 3) & 1;
  const int axor = l & 7, bxor = l & 7;

  // K i-tile (plain loads, once): 64 rows -> 512 chunks, 128 threads x4
  #pragma unroll
  for (int u = 0; u < 4; u++) {
    const int idx = tid + 128*u;
    const int row = idx >> 3, c = idx & 7;
    const uint32_t go = (uint32_t)(it*64 + row)*128 + c*16;
    const uint32_t so = (uint32_t)row*128 + (uint32_t)((c ^ (row & 7)) << 4);
    *(uint4*)(smc + OFF_KH + so) = *(const uint4*)(Khg + go);
  }

  // prologue: prefetch jt=0 into buffer 0
  #pragma unroll
  for (int u = 0; u < 4; u++) {
    const int idx = tid + 128*u;
    const int row = idx >> 3, c = idx & 7;
    const uint32_t go = (uint32_t)row*128 + c*16;
    const uint32_t so = (uint32_t)row*128 + (uint32_t)((c ^ (row & 7)) << 4);
    cpa16(sb + OFF_Q + so, Qg + go);
    cpa16(sb + OFF_V + so, Vg + go);
  }
  asm volatile("cp.async.commit_group;" ::: "memory");

  float zacc[8][4] = {};
  float lrow[2] = {0.f, 0.f};

  for (int jt = 0; jt < 32; jt++) {
    const uint32_t qb = sb + OFF_Q + (uint32_t)(jt & 1)*8192;
    const uint32_t vb = sb + OFF_V + (uint32_t)(jt & 1)*8192;

    asm volatile("cp.async.wait_group 0;" ::: "memory");
    __syncthreads();

    if (jt < 31) {
      const uint32_t qn = sb + OFF_Q + (uint32_t)((jt + 1) & 1)*8192;
      const uint32_t vn = sb + OFF_V + (uint32_t)((jt + 1) & 1)*8192;
      #pragma unroll
      for (int u = 0; u < 4; u++) {
        const int idx = tid + 128*u;
        const int row = idx >> 3, c = idx & 7;
        const uint32_t go = (uint32_t)((jt + 1)*64 + row)*128 + c*16;
        const uint32_t so = (uint32_t)row*128 + (uint32_t)((c ^ (row & 7)) << 4);
        cpa16(qn + so, Qg + go);
        cpa16(vn + so, Vg + go);
      }
      asm volatile("cp.async.commit_group;" ::: "memory");
    }

    // ---- S = K . Q^T ----
    float sacc[8][4] = {};
    #pragma unroll
    for (int ks = 0; ks < 4; ks++) {
      const int kc = 2*ks;
      uint32_t a[4];
      const uint32_t ac = (uint32_t)(((kc + achk) ^ axor) << 4);
      const uint32_t bc = (uint32_t)(((kc + bchk) ^ bxor) << 4);
      ldmat4(a, sKh + (uint32_t)(w*16 + arow)*128 + ac);
      #pragma unroll
      for (int jb = 0; jb < 4; jb++) {
        uint32_t q[4];
        ldmat4(q, qb + (uint32_t)(jb*16 + brow)*128 + bc);
        mma16816(sacc[2*jb],   a, q[0], q[1]);
        mma16816(sacc[2*jb+1], a, q[2], q[3]);
      }
    }

    // ---- softmax (no max) in registers; P packed as A-fragments ----
    uint32_t pa[8], pb[8];
    #pragma unroll
    for (int nt = 0; nt < 8; nt++) {
      const float p0 = __expf(sacc[nt][0] * 0.125f);
      const float p1 = __expf(sacc[nt][1] * 0.125f);
      const float p2 = __expf(sacc[nt][2] * 0.125f);
      const float p3 = __expf(sacc[nt][3] * 0.125f);
      lrow[0] += p0 + p1;
      lrow[1] += p2 + p3;
      pa[nt] = pack_h2(p0, p1);
      pb[nt] = pack_h2(p2, p3);
    }

    // ---- Z += P . V ----
    #pragma unroll
    for (int kj = 0; kj < 4; kj++) {
      const uint32_t A[4] = {pa[2*kj], pb[2*kj], pa[2*kj+1], pb[2*kj+1]};
      #pragma unroll
      for (int d4 = 0; d4 < 4; d4++) {
        uint32_t v[4];
        ldmat4t(v, vb + (uint32_t)(16*kj + arow)*128 +
                   (uint32_t)(((2*d4 + achk) ^ axor) << 4));
        mma16816(zacc[2*d4],   A, v[0], v[1]);
        mma16816(zacc[2*d4+1], A, v[2], v[3]);
      }
    }
  }

  // ---- final row sums and epilogue (Zh only) ----
  #pragma unroll
  for (int h = 0; h < 2; h++) {
    float v = lrow[h];
    v += __shfl_xor_sync(0xffffffffu, v, 1);
    v += __shfl_xor_sync(0xffffffffu, v, 2);
    lrow[h] = v;
  }
  const float inv0 = 1.f / lrow[0];
  const float inv1 = 1.f / lrow[1];

  __half* Zh = g_Zh + (size_t)g*GSZ + (size_t)it*64*64;
  const int r0 = w*16 + (l >> 2);
  #pragma unroll
  for (int nt = 0; nt < 8; nt++) {
    const int c = nt*8 + 2*(l & 3);
    *(uint32_t*)(Zh + (size_t)r0*64 + c) =
        pack_h2(zacc[nt][0]*inv0, zacc[nt][1]*inv0);
    *(uint32_t*)(Zh + (size_t)(r0+8)*64 + c) =
        pack_h2(zacc[nt][2]*inv1, zacc[nt][3]*inv1);
  }
}

// ---------------------------------------------------------------------------
// out_mma: out = Zh @ (Wh + Wl) via HMMA (2-term), cp.async double-buffered.
// grid 128 (m-tile 64), block 256 (8 warps 4x2), 12 k-chunks.
// ---------------------------------------------------------------------------
#define OG_ZH 0          // double buffer, stride 8192
#define OG_WH 16384      // double buffer, stride 8192
#define OG_WL 32768      // double buffer, stride 8192
#define OG_SMEM 49152

__global__ __launch_bounds__(256) void out_mma(float* __restrict__ out) {
  extern __shared__ char smc[];
  const uint32_t sb = smem_u32(smc);
  const int mt = blockIdx.x;
  const int tid = threadIdx.x;
  const int wid = tid >> 5, l = tid & 31;
  const int wr = wid & 3, wc = wid >> 2;
  const int m0 = mt*64;

  const int arow = (l & 7) + (((l >> 3) & 1) << 3);
  const int achk = l >> 4;
  const int brow = (l & 7) + ((l >> 4) << 3);
  const int bchk = (l >> 3) & 1;
  const int axor = l & 7, bxor = l & 7;

  #pragma unroll
  for (int u = 0; u < 2; u++) {
    const int idx = tid + 256*u;
    const int row = idx >> 3, c = idx & 7;
    const uint32_t zgo = (uint32_t)(m0 + row)*1536 + c*16;
    const uint32_t wgo = (uint32_t)row*1536 + c*16;
    const uint32_t so = (uint32_t)row*128 + (uint32_t)((c ^ (row & 7)) << 4);
    cpa16(sb + OG_ZH + so, (const char*)g_Zh + zgo);
    cpa16(sb + OG_WH + so, (const char*)g_Woth + wgo);
    cpa16(sb + OG_WL + so, (const char*)g_Wotl + wgo);
  }
  asm volatile("cp.async.commit_group;" ::: "memory");

  float acc[4][4] = {};

  for (int kt = 0; kt < 12; kt++) {
    const uint32_t buf = (uint32_t)(kt & 1)*8192;
    const uint32_t sZh = sb + OG_ZH + buf;
    const uint32_t sWh = sb + OG_WH + buf, sWl = sb + OG_WL + buf;

    asm volatile("cp.async.wait_group 0;" ::: "memory");
    __syncthreads();

    if (kt < 11) {
      const uint32_t nbuf = (uint32_t)((kt + 1) & 1)*8192;
      #pragma unroll
      for (int u = 0; u < 2; u++) {
        const int idx = tid + 256*u;
        const int row = idx >> 3, c = idx & 7;
        const uint32_t zgo = (uint32_t)(m0 + row)*1536 + (uint32_t)(kt+1)*128 + c*16;
        const uint32_t wgo = (uint32_t)row*1536 + (uint32_t)(kt+1)*128 + c*16;
        const uint32_t so = (uint32_t)row*128 + (uint32_t)((c ^ (row & 7)) << 4);
        cpa16(sb + OG_ZH + nbuf + so, (const char*)g_Zh + zgo);
        cpa16(sb + OG_WH + nbuf + so, (const char*)g_Woth + wgo);
        cpa16(sb + OG_WL + nbuf + so, (const char*)g_Wotl + wgo);
      }
      asm volatile("cp.async.commit_group;" ::: "memory");
    }

    #pragma unroll
    for (int ks = 0; ks < 4; ks++) {
      const int kc = 2*ks;
      uint32_t aH[4], bH0[4], bH1[4], bL0[4], bL1[4];
      const uint32_t ac = (uint32_t)(((kc + achk) ^ axor) << 4);
      const uint32_t bc = (uint32_t)(((kc + bchk) ^ bxor) << 4);
      ldmat4(aH, sZh + (uint32_t)(wr*16 + arow)*128 + ac);
      ldmat4(bH0, sWh + (uint32_t)(wc*32      + brow)*128 + bc);
      ldmat4(bH1, sWh + (uint32_t)(wc*32 + 16 + brow)*128 + bc);
      ldmat4(bL0, sWl + (uint32_t)(wc*32      + brow)*128 + bc);
      ldmat4(bL1, sWl + (uint32_t)(wc*32 + 16 + brow)*128 + bc);
      mma16816(acc[0], aH, bH0[0], bH0[1]); mma16816(acc[1], aH, bH0[2], bH0[3]);
      mma16816(acc[2], aH, bH1[0], bH1[1]); mma16816(acc[3], aH, bH1[2], bH1[3]);
      mma16816(acc[0], aH, bL0[0], bL0[1]); mma16816(acc[1], aH, bL0[2], bL0[3]);
      mma16816(acc[2], aH, bL1[0], bL1[1]); mma16816(acc[3], aH, bL1[2], bL1[3]);
    }
  }

  const int r0 = m0 + wr*16 + (l >> 2);
  #pragma unroll
  for (int ni = 0; ni < 4; ni++) {
    const int n = wc*32 + ni*8 + 2*(l & 3);
    *(float2*)(out + (size_t)r0*64 + n)       = make_float2(acc[ni][0], acc[ni][1]);
    *(float2*)(out + (size_t)(r0 + 8)*64 + n) = make_float2(acc[ni][2], acc[ni][3]);
  }
}

// ---------------------------------------------------------------------------
extern "C" void kernel_launch(void* const* d_in, const int* in_sizes, int n_in,
                              void* d_out, int out_size) {
  const float* x  = (const float*)d_in[0];
  const float* Wq = (const float*)d_in[1];
  const float* Wk = (const float*)d_in[2];
  const float* Wv = (const float*)d_in[3];
  const float* Wo = (const float*)d_in[4];
  float* out = (float*)d_out;

  prep_all<<<304, 256>>>(x, Wq, Wk, Wv, Wo);

  cudaFuncSetAttribute(qkv_mma, cudaFuncAttributeMaxDynamicSharedMemorySize,
                       QK_SMEM);
  qkv_mma<<<dim3(12, 64, 3), 256, QK_SMEM>>>();

  cudaFuncSetAttribute(attn_mma, cudaFuncAttributeMaxDynamicSharedMemorySize,
                       SMEM_ATT);
  attn_mma<<<dim3(32, 48), 128, SMEM_ATT>>>();

  cudaFuncSetAttribute(out_mma, cudaFuncAttributeMaxDynamicSharedMemorySize,
                       OG_SMEM);
  out_mma<<<128, 256, OG_SMEM>>>(out);
}

// round 17
// speedup vs baseline: 1.5354x; 1.0002x over previous
#include <cuda_runtime.h>
#include <cuda_fp16.h>
#include <cstdint>

#define TT 2048
#define DD 64
#define NG 48
#define GSZ (TT*DD)        // 131072 elements per flat "head"

// S-scale folded into K at qkv epilogue: 0.125 * log2(e)
#define KSCALE 0.18033688011112042f

// ---- scratch (device globals; no allocation allowed) ----------------------
__device__ __half g_xh[8192*64];                        // x fp16 (hi only)
__device__ __half g_Wth[3*768*64], g_Wtl[3*768*64];     // W^T [mat][n][k] hi/lo
__device__ __half g_Woth[64*768], g_Wotl[64*768];       // Wo^T [n][k] hi/lo
__device__ __half g_Qh[(size_t)NG*GSZ];
__device__ __half g_Kh[(size_t)NG*GSZ];                 // pre-scaled by KSCALE
__device__ __half g_Vh[(size_t)NG*GSZ];
__device__ __half g_Zh[(size_t)NG*GSZ];

// ---- helpers ---------------------------------------------------------------
__device__ __forceinline__ uint32_t smem_u32(const void* p) {
  uint32_t a;
  asm("{ .reg .u64 t; cvta.to.shared.u64 t, %1; cvt.u32.u64 %0, t; }"
      : "=r"(a) : "l"(p));
  return a;
}
__device__ __forceinline__ void ldmat4(uint32_t (&r)[4], uint32_t addr) {
  asm volatile("ldmatrix.sync.aligned.m8n8.x4.shared.b16 {%0,%1,%2,%3}, [%4];"
    : "=r"(r[0]), "=r"(r[1]), "=r"(r[2]), "=r"(r[3]) : "r"(addr));
}
__device__ __forceinline__ void ldmat4t(uint32_t (&r)[4], uint32_t addr) {
  asm volatile("ldmatrix.sync.aligned.m8n8.x4.trans.shared.b16 {%0,%1,%2,%3}, [%4];"
    : "=r"(r[0]), "=r"(r[1]), "=r"(r[2]), "=r"(r[3]) : "r"(addr));
}
__device__ __forceinline__ void mma16816(float (&c)[4], const uint32_t (&a)[4],
                                         uint32_t b0, uint32_t b1) {
  asm volatile("mma.sync.aligned.m16n8k16.row.col.f32.f16.f16.f32 "
    "{%0,%1,%2,%3}, {%4,%5,%6,%7}, {%8,%9}, {%0,%1,%2,%3};"
    : "+f"(c[0]), "+f"(c[1]), "+f"(c[2]), "+f"(c[3])
    : "r"(a[0]), "r"(a[1]), "r"(a[2]), "r"(a[3]), "r"(b0), "r"(b1));
}
__device__ __forceinline__ uint32_t pack_h2(float a, float b) {
  __half2 h = __floats2half2_rn(a, b);
  return *(uint32_t*)&h;
}
__device__ __forceinline__ void cpa16(uint32_t s, const void* g) {
  asm volatile("cp.async.cg.shared.global [%0], [%1], 16;" :: "r"(s), "l"(g));
}
__device__ __forceinline__ float ex2(float x) {
  float r;
  asm("ex2.approx.f32 %0, %1;" : "=f"(r) : "f"(x));
  return r;
}

// ---------------------------------------------------------------------------
// prep_all: one launch for all preprocessing.
//   blocks [0,256):   x fp32 -> g_xh fp16 (hi only)
//   blocks [256,292): W{q,k,v} -> Wt [mat][n][k] fp16 hi/lo
//   blocks [292,304): Wo -> Wot [64][768] fp16 hi/lo
// ---------------------------------------------------------------------------
__global__ __launch_bounds__(256) void prep_all(
    const float* __restrict__ x,  const float* __restrict__ Wq,
    const float* __restrict__ Wk, const float* __restrict__ Wv,
    const float* __restrict__ Wo) {
  __shared__ float s[64*65];
  const int bid = blockIdx.x;
  const int tid = threadIdx.x;

  if (bid < 256) {
    const int t = bid*256 + tid;
    const float4 v0 = *(const float4*)(x + t*8);
    const float4 v1 = *(const float4*)(x + t*8 + 4);
    uint32_t h[4];
    h[0] = pack_h2(v0.x, v0.y); h[1] = pack_h2(v0.z, v0.w);
    h[2] = pack_h2(v1.x, v1.y); h[3] = pack_h2(v1.z, v1.w);
    *(uint4*)(g_xh + t*8) = make_uint4(h[0], h[1], h[2], h[3]);
    return;
  }

  if (bid < 292) {
    const int idx = bid - 256;
    const int nt = idx % 12, mat = idx / 12;
    const float* W = (mat == 0) ? Wq : ((mat == 1) ? Wk : Wv);
    const int n0 = nt*64;
    #pragma unroll
    for (int u = 0; u < 4; u++) {
      const int id2 = tid + 256*u;
      const int k = id2 >> 4, c4 = id2 & 15;
      const float4 v = *(const float4*)(W + k*768 + n0 + c4*4);
      s[(c4*4+0)*65 + k] = v.x; s[(c4*4+1)*65 + k] = v.y;
      s[(c4*4+2)*65 + k] = v.z; s[(c4*4+3)*65 + k] = v.w;
    }
    __syncthreads();
    const int n = tid >> 2, k0 = (tid & 3) * 16;
    uint32_t h[8], l[8];
    #pragma unroll
    for (int i = 0; i < 8; i++) {
      const float a = s[n*65 + k0 + 2*i], b = s[n*65 + k0 + 2*i + 1];
      const float ha = __half2float(__float2half_rn(a));
      const float hb = __half2float(__float2half_rn(b));
      h[i] = pack_h2(a, b);
      l[i] = pack_h2(a - ha, b - hb);
    }
    __half* dh = g_Wth + (size_t)(mat*768 + n0 + n)*64 + k0;
    __half* dl = g_Wtl + (size_t)(mat*768 + n0 + n)*64 + k0;
    ((uint4*)dh)[0] = make_uint4(h[0], h[1], h[2], h[3]);
    ((uint4*)dh)[1] = make_uint4(h[4], h[5], h[6], h[7]);
    ((uint4*)dl)[0] = make_uint4(l[0], l[1], l[2], l[3]);
    ((uint4*)dl)[1] = make_uint4(l[4], l[5], l[6], l[7]);
    return;
  }

  {
    const int kt = bid - 292;
    const int k0g = kt*64;
    #pragma unroll
    for (int u = 0; u < 4; u++) {
      const int id2 = tid + 256*u;
      const int k = id2 >> 4, c4 = id2 & 15;
      const float4 v = *(const float4*)(Wo + (size_t)(k0g + k)*64 + c4*4);
      s[(c4*4+0)*65 + k] = v.x; s[(c4*4+1)*65 + k] = v.y;
      s[(c4*4+2)*65 + k] = v.z; s[(c4*4+3)*65 + k] = v.w;
    }
    __syncthreads();
    const int n = tid >> 2, k0 = (tid & 3) * 16;
    uint32_t h[8], l[8];
    #pragma unroll
    for (int i = 0; i < 8; i++) {
      const float a = s[n*65 + k0 + 2*i], b = s[n*65 + k0 + 2*i + 1];
      const float ha = __half2float(__float2half_rn(a));
      const float hb = __half2float(__float2half_rn(b));
      h[i] = pack_h2(a, b);
      l[i] = pack_h2(a - ha, b - hb);
    }
    __half* dh = g_Woth + (size_t)n*768 + k0g + k0;
    __half* dl = g_Wotl + (size_t)n*768 + k0g + k0;
    ((uint4*)dh)[0] = make_uint4(h[0], h[1], h[2], h[3]);
    ((uint4*)dh)[1] = make_uint4(h[4], h[5], h[6], h[7]);
    ((uint4*)dl)[0] = make_uint4(l[0], l[1], l[2], l[3]);
    ((uint4*)dl)[1] = make_uint4(l[4], l[5], l[6], l[7]);
  }
}

// ---------------------------------------------------------------------------
// qkv_mma: QKV = xh @ (Wh + Wl) via HMMA (2-term split; x lo dropped).
// K output pre-scaled by KSCALE (softmax scale folded in).
// grid (12 nt, 64 mt, 3 mat), block 256, tile 128m x 64n.
// ---------------------------------------------------------------------------
#define QK_XH 0
#define QK_WH 16384
#define QK_WL 24576
#define QK_SMEM 32768

__global__ __launch_bounds__(256) void qkv_mma() {
  extern __shared__ char smc[];
  const uint32_t sb = smem_u32(smc);
  const uint32_t sXh = sb + QK_XH;
  const uint32_t sWh = sb + QK_WH, sWl = sb + QK_WL;
  const int nt = blockIdx.x, mt = blockIdx.y, mat = blockIdx.z;
  const int tid = threadIdx.x;
  const int wid = tid >> 5, l = tid & 31;
  const int wr = wid & 3, wc = wid >> 2;
  const int m0 = mt*128, n0 = nt*64;

  const int arow = (l & 7) + (((l >> 3) & 1) << 3);
  const int achk = l >> 4;
  const int brow = (l & 7) + ((l >> 4) << 3);
  const int bchk = (l >> 3) & 1;
  const int axor = l & 7, bxor = l & 7;

  #pragma unroll
  for (int u = 0; u < 4; u++) {
    const int idx = tid + 256*u;
    const int row = idx >> 3, c = idx & 7;
    const uint32_t go = (uint32_t)(m0 + row)*128 + c*16;
    const uint32_t so = (uint32_t)row*128 + (uint32_t)((c ^ (row & 7)) << 4);
    *(uint4*)(smc + QK_XH + so) = *(const uint4*)((const char*)g_xh + go);
  }
  #pragma unroll
  for (int u = 0; u < 2; u++) {
    const int idx = tid + 256*u;
    const int row = idx >> 3, c = idx & 7;
    const uint32_t go = (uint32_t)(mat*768 + n0 + row)*128 + c*16;
    const uint32_t so = (uint32_t)row*128 + (uint32_t)((c ^ (row & 7)) << 4);
    *(uint4*)(smc + QK_WH + so) = *(const uint4*)((const char*)g_Wth + go);
    *(uint4*)(smc + QK_WL + so) = *(const uint4*)((const char*)g_Wtl + go);
  }
  __syncthreads();

  float acc[2][4][4] = {};
  #pragma unroll
  for (int ks = 0; ks < 4; ks++) {
    const int kc = 2*ks;
    uint32_t aH0[4], aH1[4], bH0[4], bH1[4], bL0[4], bL1[4];
    const uint32_t ac = (uint32_t)(((kc + achk) ^ axor) << 4);
    const uint32_t bc = (uint32_t)(((kc + bchk) ^ bxor) << 4);
    ldmat4(aH0, sXh + (uint32_t)(wr*32      + arow)*128 + ac);
    ldmat4(aH1, sXh + (uint32_t)(wr*32 + 16 + arow)*128 + ac);
    ldmat4(bH0, sWh + (uint32_t)(wc*32      + brow)*128 + bc);
    ldmat4(bH1, sWh + (uint32_t)(wc*32 + 16 + brow)*128 + bc);
    ldmat4(bL0, sWl + (uint32_t)(wc*32      + brow)*128 + bc);
    ldmat4(bL1, sWl + (uint32_t)(wc*32 + 16 + brow)*128 + bc);
    mma16816(acc[0][0], aH0, bH0[0], bH0[1]); mma16816(acc[0][1], aH0, bH0[2], bH0[3]);
    mma16816(acc[0][2], aH0, bH1[0], bH1[1]); mma16816(acc[0][3], aH0, bH1[2], bH1[3]);
    mma16816(acc[1][0], aH1, bH0[0], bH0[1]); mma16816(acc[1][1], aH1, bH0[2], bH0[3]);
    mma16816(acc[1][2], aH1, bH1[0], bH1[1]); mma16816(acc[1][3], aH1, bH1[2], bH1[3]);
    mma16816(acc[0][0], aH0, bL0[0], bL0[1]); mma16816(acc[0][1], aH0, bL0[2], bL0[3]);
    mma16816(acc[0][2], aH0, bL1[0], bL1[1]); mma16816(acc[0][3], aH0, bL1[2], bL1[3]);
    mma16816(acc[1][0], aH1, bL0[0], bL0[1]); mma16816(acc[1][1], aH1, bL0[2], bL0[3]);
    mma16816(acc[1][2], aH1, bL1[0], bL1[1]); mma16816(acc[1][3], aH1, bL1[2], bL1[3]);
  }

  #pragma unroll
  for (int mi = 0; mi < 2; mi++) {
    const int r0 = wr*32 + mi*16 + (l >> 2);
    #pragma unroll
    for (int ni = 0; ni < 4; ni++) {
      const int d = wc*32 + ni*8 + 2*(l & 3);
      #pragma unroll
      for (int hh = 0; hh < 2; hh++) {
        const int r = r0 + 8*hh;
        const float a = acc[mi][ni][2*hh+0], bb = acc[mi][ni][2*hh+1];
        const size_t off = (size_t)(m0 + r)*768 + n0 + d;
        if (mat == 0) {
          *(uint32_t*)(g_Qh + off) = pack_h2(a, bb);
        } else if (mat == 1) {
          *(uint32_t*)(g_Kh + off) = pack_h2(a*KSCALE, bb*KSCALE);
        } else {
          *(uint32_t*)(g_Vh + off) = pack_h2(a, bb);
        }
      }
    }
  }
}

// ---------------------------------------------------------------------------
// HMMA flash attention, register-resident P, 4-CTA-per-SM config.
// S already includes the softmax scale (K pre-scaled), so P = ex2(S) directly.
// grid (32 i-tiles, 48 heads), 128 threads = 4 warps.
// ---------------------------------------------------------------------------
#define OFF_KH 0         // 8KB (64 rows)
#define OFF_Q  8192      // double buffer, stride 8192
#define OFF_V  24576     // double buffer, stride 8192
#define SMEM_ATT 40960

__global__ __launch_bounds__(128, 4) void attn_mma() {
  extern __shared__ char smc[];
  const uint32_t sb = smem_u32(smc);
  const uint32_t sKh = sb + OFF_KH;

  const int g = blockIdx.y, it = blockIdx.x;
  const int tid = threadIdx.x;
  const int w = tid >> 5, l = tid & 31;

  const char* Qg  = (const char*)(g_Qh + (size_t)g*GSZ);
  const char* Khg = (const char*)(g_Kh + (size_t)g*GSZ);
  const char* Vg  = (const char*)(g_Vh + (size_t)g*GSZ);

  const int arow = (l & 7) + (((l >> 3) & 1) << 3);
  const int achk = l >> 4;
  const int brow = (l & 7) + ((l >> 4) << 3);
  const int bchk = (l >> 3) & 1;
  const int axor = l & 7, bxor = l & 7;

  // K i-tile (plain loads, once)
  #pragma unroll
  for (int u = 0; u < 4; u++) {
    const int idx = tid + 128*u;
    const int row = idx >> 3, c = idx & 7;
    const uint32_t go = (uint32_t)(it*64 + row)*128 + c*16;
    const uint32_t so = (uint32_t)row*128 + (uint32_t)((c ^ (row & 7)) << 4);
    *(uint4*)(smc + OFF_KH + so) = *(const uint4*)(Khg + go);
  }

  // prologue: prefetch jt=0 into buffer 0
  #pragma unroll
  for (int u = 0; u < 4; u++) {
    const int idx = tid + 128*u;
    const int row = idx >> 3, c = idx & 7;
    const uint32_t go = (uint32_t)row*128 + c*16;
    const uint32_t so = (uint32_t)row*128 + (uint32_t)((c ^ (row & 7)) << 4);
    cpa16(sb + OFF_Q + so, Qg + go);
    cpa16(sb + OFF_V + so, Vg + go);
  }
  asm volatile("cp.async.commit_group;" ::: "memory");

  float zacc[8][4] = {};
  float lrow[2] = {0.f, 0.f};

  for (int jt = 0; jt < 32; jt++) {
    const uint32_t qb = sb + OFF_Q + (uint32_t)(jt & 1)*8192;
    const uint32_t vb = sb + OFF_V + (uint32_t)(jt & 1)*8192;

    asm volatile("cp.async.wait_group 0;" ::: "memory");
    __syncthreads();

    if (jt < 31) {
      const uint32_t qn = sb + OFF_Q + (uint32_t)((jt + 1) & 1)*8192;
      const uint32_t vn = sb + OFF_V + (uint32_t)((jt + 1) & 1)*8192;
      #pragma unroll
      for (int u = 0; u < 4; u++) {
        const int idx = tid + 128*u;
        const int row = idx >> 3, c = idx & 7;
        const uint32_t go = (uint32_t)((jt + 1)*64 + row)*128 + c*16;
        const uint32_t so = (uint32_t)row*128 + (uint32_t)((c ^ (row & 7)) << 4);
        cpa16(qn + so, Qg + go);
        cpa16(vn + so, Vg + go);
      }
      asm volatile("cp.async.commit_group;" ::: "memory");
    }

    // ---- S = (cK) . Q^T ----
    float sacc[8][4] = {};
    #pragma unroll
    for (int ks = 0; ks < 4; ks++) {
      const int kc = 2*ks;
      uint32_t a[4];
      const uint32_t ac = (uint32_t)(((kc + achk) ^ axor) << 4);
      const uint32_t bc = (uint32_t)(((kc + bchk) ^ bxor) << 4);
      ldmat4(a, sKh + (uint32_t)(w*16 + arow)*128 + ac);
      #pragma unroll
      for (int jb = 0; jb < 4; jb++) {
        uint32_t q[4];
        ldmat4(q, qb + (uint32_t)(jb*16 + brow)*128 + bc);
        mma16816(sacc[2*jb],   a, q[0], q[1]);
        mma16816(sacc[2*jb+1], a, q[2], q[3]);
      }
    }

    // ---- softmax: p = 2^S directly (scale folded into K) ----
    uint32_t pa[8], pb[8];
    #pragma unroll
    for (int nt = 0; nt < 8; nt++) {
      const float p0 = ex2(sacc[nt][0]);
      const float p1 = ex2(sacc[nt][1]);
      const float p2 = ex2(sacc[nt][2]);
      const float p3 = ex2(sacc[nt][3]);
      lrow[0] += p0 + p1;
      lrow[1] += p2 + p3;
      pa[nt] = pack_h2(p0, p1);
      pb[nt] = pack_h2(p2, p3);
    }

    // ---- Z += P . V ----
    #pragma unroll
    for (int kj = 0; kj < 4; kj++) {
      const uint32_t A[4] = {pa[2*kj], pb[2*kj], pa[2*kj+1], pb[2*kj+1]};
      #pragma unroll
      for (int d4 = 0; d4 < 4; d4++) {
        uint32_t v[4];
        ldmat4t(v, vb + (uint32_t)(16*kj + arow)*128 +
                   (uint32_t)(((2*d4 + achk) ^ axor) << 4));
        mma16816(zacc[2*d4],   A, v[0], v[1]);
        mma16816(zacc[2*d4+1], A, v[2], v[3]);
      }
    }
  }

  // ---- final row sums and epilogue (Zh only) ----
  #pragma unroll
  for (int h = 0; h < 2; h++) {
    float v = lrow[h];
    v += __shfl_xor_sync(0xffffffffu, v, 1);
    v += __shfl_xor_sync(0xffffffffu, v, 2);
    lrow[h] = v;
  }
  const float inv0 = 1.f / lrow[0];
  const float inv1 = 1.f / lrow[1];

  __half* Zh = g_Zh + (size_t)g*GSZ + (size_t)it*64*64;
  const int r0 = w*16 + (l >> 2);
  #pragma unroll
  for (int nt = 0; nt < 8; nt++) {
    const int c = nt*8 + 2*(l & 3);
    *(uint32_t*)(Zh + (size_t)r0*64 + c) =
        pack_h2(zacc[nt][0]*inv0, zacc[nt][1]*inv0);
    *(uint32_t*)(Zh + (size_t)(r0+8)*64 + c) =
        pack_h2(zacc[nt][2]*inv1, zacc[nt][3]*inv1);
  }
}

// ---------------------------------------------------------------------------
// out_mma: out = Zh @ (Wh + Wl) via HMMA (2-term), cp.async double-buffered.
// grid 128 (m-tile 64), block 256 (8 warps 4x2), 12 k-chunks.
// ---------------------------------------------------------------------------
#define OG_ZH 0          // double buffer, stride 8192
#define OG_WH 16384      // double buffer, stride 8192
#define OG_WL 32768      // double buffer, stride 8192
#define OG_SMEM 49152

__global__ __launch_bounds__(256) void out_mma(float* __restrict__ out) {
  extern __shared__ char smc[];
  const uint32_t sb = smem_u32(smc);
  const int mt = blockIdx.x;
  const int tid = threadIdx.x;
  const int wid = tid >> 5, l = tid & 31;
  const int wr = wid & 3, wc = wid >> 2;
  const int m0 = mt*64;

  const int arow = (l & 7) + (((l >> 3) & 1) << 3);
  const int achk = l >> 4;
  const int brow = (l & 7) + ((l >> 4) << 3);
  const int bchk = (l >> 3) & 1;
  const int axor = l & 7, bxor = l & 7;

  #pragma unroll
  for (int u = 0; u < 2; u++) {
    const int idx = tid + 256*u;
    const int row = idx >> 3, c = idx & 7;
    const uint32_t zgo = (uint32_t)(m0 + row)*1536 + c*16;
    const uint32_t wgo = (uint32_t)row*1536 + c*16;
    const uint32_t so = (uint32_t)row*128 + (uint32_t)((c ^ (row & 7)) << 4);
    cpa16(sb + OG_ZH + so, (const char*)g_Zh + zgo);
    cpa16(sb + OG_WH + so, (const char*)g_Woth + wgo);
    cpa16(sb + OG_WL + so, (const char*)g_Wotl + wgo);
  }
  asm volatile("cp.async.commit_group;" ::: "memory");

  float acc[4][4] = {};

  for (int kt = 0; kt < 12; kt++) {
    const uint32_t buf = (uint32_t)(kt & 1)*8192;
    const uint32_t sZh = sb + OG_ZH + buf;
    const uint32_t sWh = sb + OG_WH + buf, sWl = sb + OG_WL + buf;

    asm volatile("cp.async.wait_group 0;" ::: "memory");
    __syncthreads();

    if (kt < 11) {
      const uint32_t nbuf = (uint32_t)((kt + 1) & 1)*8192;
      #pragma unroll
      for (int u = 0; u < 2; u++) {
        const int idx = tid + 256*u;
        const int row = idx >> 3, c = idx & 7;
        const uint32_t zgo = (uint32_t)(m0 + row)*1536 + (uint32_t)(kt+1)*128 + c*16;
        const uint32_t wgo = (uint32_t)row*1536 + (uint32_t)(kt+1)*128 + c*16;
        const uint32_t so = (uint32_t)row*128 + (uint32_t)((c ^ (row & 7)) << 4);
        cpa16(sb + OG_ZH + nbuf + so, (const char*)g_Zh + zgo);
        cpa16(sb + OG_WH + nbuf + so, (const char*)g_Woth + wgo);
        cpa16(sb + OG_WL + nbuf + so, (const char*)g_Wotl + wgo);
      }
      asm volatile("cp.async.commit_group;" ::: "memory");
    }

    #pragma unroll
    for (int ks = 0; ks < 4; ks++) {
      const int kc = 2*ks;
      uint32_t aH[4], bH0[4], bH1[4], bL0[4], bL1[4];
      const uint32_t ac = (uint32_t)(((kc + achk) ^ axor) << 4);
      const uint32_t bc = (uint32_t)(((kc + bchk) ^ bxor) << 4);
      ldmat4(aH, sZh + (uint32_t)(wr*16 + arow)*128 + ac);
      ldmat4(bH0, sWh + (uint32_t)(wc*32      + brow)*128 + bc);
      ldmat4(bH1, sWh + (uint32_t)(wc*32 + 16 + brow)*128 + bc);
      ldmat4(bL0, sWl + (uint32_t)(wc*32      + brow)*128 + bc);
      ldmat4(bL1, sWl + (uint32_t)(wc*32 + 16 + brow)*128 + bc);
      mma16816(acc[0], aH, bH0[0], bH0[1]); mma16816(acc[1], aH, bH0[2], bH0[3]);
      mma16816(acc[2], aH, bH1[0], bH1[1]); mma16816(acc[3], aH, bH1[2], bH1[3]);
      mma16816(acc[0], aH, bL0[0], bL0[1]); mma16816(acc[1], aH, bL0[2], bL0[3]);
      mma16816(acc[2], aH, bL1[0], bL1[1]); mma16816(acc[3], aH, bL1[2], bL1[3]);
    }
  }

  const int r0 = m0 + wr*16 + (l >> 2);
  #pragma unroll
  for (int ni = 0; ni < 4; ni++) {
    const int n = wc*32 + ni*8 + 2*(l & 3);
    *(float2*)(out + (size_t)r0*64 + n)       = make_float2(acc[ni][0], acc[ni][1]);
    *(float2*)(out + (size_t)(r0 + 8)*64 + n) = make_float2(acc[ni][2], acc[ni][3]);
  }
}

// ---------------------------------------------------------------------------
extern "C" void kernel_launch(void* const* d_in, const int* in_sizes, int n_in,
                              void* d_out, int out_size) {
  const float* x  = (const float*)d_in[0];
  const float* Wq = (const float*)d_in[1];
  const float* Wk = (const float*)d_in[2];
  const float* Wv = (const float*)d_in[3];
  const float* Wo = (const float*)d_in[4];
  float* out = (float*)d_out;

  prep_all<<<304, 256>>>(x, Wq, Wk, Wv, Wo);

  cudaFuncSetAttribute(qkv_mma, cudaFuncAttributeMaxDynamicSharedMemorySize,
                       QK_SMEM);
  qkv_mma<<<dim3(12, 64, 3), 256, QK_SMEM>>>();

  cudaFuncSetAttribute(attn_mma, cudaFuncAttributeMaxDynamicSharedMemorySize,
                       SMEM_ATT);
  attn_mma<<<dim3(32, 48), 128, SMEM_ATT>>>();

  cudaFuncSetAttribute(out_mma, cudaFuncAttributeMaxDynamicSharedMemorySize,
                       OG_SMEM);
  out_mma<<<128, 256, OG_SMEM>>>(out);
}